// round 1
// baseline (speedup 1.0000x reference)
#include <cuda_runtime.h>
#include <math.h>

// ---------------------------------------------------------------------------
// Problem constants
// ---------------------------------------------------------------------------
#define NB   8192           // batch B
#define NT   8192           // targets T
#define FD   768            // F_DIM
#define PD   512            // P_DIM
#define HD   1024           // H_DIM
#define NE   4              // N_EXP
#define TWOP 1024           // 2*P_DIM
#define RHD  256            // H_DIM/4

#define LOGITS_ELEMS (8192ull*8192ull)
#define DS_OFF  (8192ull*8192ull)              // 67108864
#define PR_OFF  (8192ull*8192ull + 8192ull)    // 67117056

typedef unsigned long long u64;

// ---------------------------------------------------------------------------
// Scratch (device globals: allocation-free)
// ---------------------------------------------------------------------------
__device__ float g_comb [8192ull*1024];   // [B, 2P]  (tp | ip)
__device__ float g_rh   [8192ull*256];    // router hidden
__device__ float g_eo   [8192ull*4096];   // expert outputs, gelu'd, [B, E*H]
__device__ float g_fused[8192ull*1024];   // fused hidden
__device__ float g_dh   [8192ull*1024];   // ds hidden
__device__ float g_resid[8192ull*768];    // residual
__device__ float g_pred [8192ull*768];    // normalized prediction
__device__ float g_tgt  [8192ull*768];    // normalized targets
__device__ float g_probs[8192ull*4];      // router probs
__device__ float g_ds   [8192];           // dynamic scalar

// ---------------------------------------------------------------------------
// f32x2 packed math helpers (Blackwell: FFMA2 only reachable via PTX)
// ---------------------------------------------------------------------------
__device__ __forceinline__ u64 pk2(float lo, float hi) {
    u64 r; asm("mov.b64 %0, {%1,%2};" : "=l"(r) : "f"(lo), "f"(hi)); return r;
}
__device__ __forceinline__ float2 up2(u64 v) {
    float2 f; asm("mov.b64 {%0,%1}, %2;" : "=f"(f.x), "=f"(f.y) : "l"(v)); return f;
}
__device__ __forceinline__ u64 ffma2(u64 a, u64 b, u64 c) {
    u64 d; asm("fma.rn.f32x2 %0, %1, %2, %3;" : "=l"(d) : "l"(a), "l"(b), "l"(c)); return d;
}

__device__ __forceinline__ float gelu_exact(float x) {
    return 0.5f * x * (1.0f + erff(x * 0.70710678118654752440f));
}

// ---------------------------------------------------------------------------
// Generic SGEMM: C[M,N] = epilogue( A[M,K] @ B[N,K]^T )
//   A, B row-major. M % 128 == 0, N % 128 == 0, K % 16 == 0 (all hold here).
//   EPI: 0 = gelu(acc + bias[n]),  1 = acc + bias[n],  2 = exp(*scale_p)*acc
// Tile: 128x128x16, 256 threads, 8x8 per thread, f32x2 packed accumulate.
// ---------------------------------------------------------------------------
#define BM 128
#define BN 128
#define BK 16
#define TM 8
#define TN 8

template <int EPI>
__global__ __launch_bounds__(256) void sgemm_kernel(
    const float* __restrict__ A, const float* __restrict__ Bw,
    float* __restrict__ C, int K, int ldc, int coloff,
    const float* __restrict__ bias, const float* __restrict__ scale_p)
{
    __shared__ float As[BK][BM + 4];
    __shared__ float Bs[BK][BN + 4];

    const int bm = blockIdx.y * BM;
    const int bn = blockIdx.x * BN;
    const int t  = threadIdx.x;
    const int tx = t & 15;        // 0..15 -> N
    const int ty = t >> 4;        // 0..15 -> M

    u64 acc[TM][TN / 2];
    #pragma unroll
    for (int i = 0; i < TM; i++)
        #pragma unroll
        for (int j = 0; j < TN / 2; j++) acc[i][j] = 0ull;

    const int row0 = t >> 2;      // 0..63
    const int c4   = t & 3;       // 0..3 (float4 within the 16-wide k slab)
    const float* Ap = A  + (u64)(bm + row0) * K + c4 * 4;
    const float* Bp = Bw + (u64)(bn + row0) * K + c4 * 4;

    for (int kb = 0; kb < K; kb += BK) {
        #pragma unroll
        for (int r = 0; r < 2; r++) {
            const int row = row0 + r * 64;
            float4 va = *(const float4*)(Ap + (u64)r * 64 * K + kb);
            float4 vb = *(const float4*)(Bp + (u64)r * 64 * K + kb);
            As[c4 * 4 + 0][row] = va.x; As[c4 * 4 + 1][row] = va.y;
            As[c4 * 4 + 2][row] = va.z; As[c4 * 4 + 3][row] = va.w;
            Bs[c4 * 4 + 0][row] = vb.x; Bs[c4 * 4 + 1][row] = vb.y;
            Bs[c4 * 4 + 2][row] = vb.z; Bs[c4 * 4 + 3][row] = vb.w;
        }
        __syncthreads();

        #pragma unroll
        for (int k = 0; k < BK; k++) {
            float4 a0 = *(const float4*)&As[k][ty * TM];
            float4 a1 = *(const float4*)&As[k][ty * TM + 4];
            float4 b0 = *(const float4*)&Bs[k][tx * TN];
            float4 b1 = *(const float4*)&Bs[k][tx * TN + 4];
            u64 bb[4] = { pk2(b0.x, b0.y), pk2(b0.z, b0.w),
                          pk2(b1.x, b1.y), pk2(b1.z, b1.w) };
            float ar[8] = { a0.x, a0.y, a0.z, a0.w, a1.x, a1.y, a1.z, a1.w };
            #pragma unroll
            for (int i = 0; i < TM; i++) {
                u64 aa = pk2(ar[i], ar[i]);
                #pragma unroll
                for (int j = 0; j < TN / 2; j++)
                    acc[i][j] = ffma2(aa, bb[j], acc[i][j]);
            }
        }
        __syncthreads();
    }

    float scale = 1.0f;
    if (EPI == 2) scale = expf(*scale_p);

    #pragma unroll
    for (int i = 0; i < TM; i++) {
        const int r = bm + ty * TM + i;
        float out[TN];
        #pragma unroll
        for (int j = 0; j < TN / 2; j++) {
            float2 v = up2(acc[i][j]);
            out[2 * j] = v.x; out[2 * j + 1] = v.y;
        }
        #pragma unroll
        for (int j = 0; j < TN; j++) {
            const int n = bn + tx * TN + j;
            float v = out[j];
            if (EPI == 0)      v = gelu_exact(v + bias[n]);
            else if (EPI == 1) v = v + bias[n];
            else               v = v * scale;
            out[j] = v;
        }
        float4* cp = (float4*)(C + (u64)r * ldc + coloff + bn + tx * TN);
        cp[0] = make_float4(out[0], out[1], out[2], out[3]);
        cp[1] = make_float4(out[4], out[5], out[6], out[7]);
    }
}

// ---------------------------------------------------------------------------
// Router: logits = rh @ rt_W2^T + b2 ; softmax -> probs (scratch + d_out)
// One warp per row.
// ---------------------------------------------------------------------------
__global__ void router_kernel(const float* __restrict__ rh,
                              const float* __restrict__ W2,
                              const float* __restrict__ b2,
                              float* __restrict__ probs,
                              float* __restrict__ out_probs)
{
    int warp = (blockIdx.x * blockDim.x + threadIdx.x) >> 5;
    int lane = threadIdx.x & 31;
    if (warp >= NB) return;
    const float* r = rh + (u64)warp * RHD;
    float s0 = 0.f, s1 = 0.f, s2 = 0.f, s3 = 0.f;
    #pragma unroll
    for (int i = 0; i < RHD / 32; i++) {
        int c = lane + i * 32;
        float v = r[c];
        s0 += v * W2[c];
        s1 += v * W2[RHD + c];
        s2 += v * W2[2 * RHD + c];
        s3 += v * W2[3 * RHD + c];
    }
    #pragma unroll
    for (int o = 16; o > 0; o >>= 1) {
        s0 += __shfl_xor_sync(0xffffffffu, s0, o);
        s1 += __shfl_xor_sync(0xffffffffu, s1, o);
        s2 += __shfl_xor_sync(0xffffffffu, s2, o);
        s3 += __shfl_xor_sync(0xffffffffu, s3, o);
    }
    if (lane == 0) {
        float l0 = s0 + b2[0], l1 = s1 + b2[1], l2 = s2 + b2[2], l3 = s3 + b2[3];
        float m  = fmaxf(fmaxf(l0, l1), fmaxf(l2, l3));
        float e0 = expf(l0 - m), e1 = expf(l1 - m), e2 = expf(l2 - m), e3 = expf(l3 - m);
        float inv = 1.f / (e0 + e1 + e2 + e3);
        float4 p = make_float4(e0 * inv, e1 * inv, e2 * inv, e3 * inv);
        *(float4*)(probs + (u64)warp * 4) = p;
        *(float4*)(out_probs + (u64)warp * 4) = p;
    }
}

// ---------------------------------------------------------------------------
// ds = sigmoid(dh . W2 + b2). One warp per row.
// ---------------------------------------------------------------------------
__global__ void ds_kernel(const float* __restrict__ dh,
                          const float* __restrict__ W2,
                          const float* __restrict__ b2,
                          float* __restrict__ ds,
                          float* __restrict__ out_ds)
{
    int warp = (blockIdx.x * blockDim.x + threadIdx.x) >> 5;
    int lane = threadIdx.x & 31;
    if (warp >= NB) return;
    const float* r = dh + (u64)warp * HD;
    float s = 0.f;
    #pragma unroll
    for (int i = 0; i < HD / 32; i++) {
        int c = lane + i * 32;
        s += r[c] * W2[c];
    }
    #pragma unroll
    for (int o = 16; o > 0; o >>= 1) s += __shfl_xor_sync(0xffffffffu, s, o);
    if (lane == 0) {
        float x  = s + b2[0];
        float sg = 1.f / (1.f + expf(-x));
        ds[warp] = sg;
        out_ds[warp] = sg;
    }
}

// ---------------------------------------------------------------------------
// fused[b,h] = sum_e probs[b,e] * eo[b, e*H + h]
// ---------------------------------------------------------------------------
__global__ void expert_reduce_kernel(const float* __restrict__ eo,
                                     const float* __restrict__ probs,
                                     float* __restrict__ fused)
{
    u64 idx = (u64)blockIdx.x * blockDim.x + threadIdx.x;
    if (idx >= (u64)NB * HD) return;
    u64 b = idx >> 10;          // / HD
    u64 h = idx & 1023u;        // % HD
    const float* p = probs + b * 4;
    const float* e = eo + b * (u64)(NE * HD) + h;
    fused[idx] = p[0] * e[0] + p[1] * e[HD] + p[2] * e[2 * HD] + p[3] * e[3 * HD];
}

// ---------------------------------------------------------------------------
// pred = normalize( ds*text + (1-ds)*image + resid ), one block per row (768)
// ---------------------------------------------------------------------------
__global__ __launch_bounds__(256) void fuse_norm_kernel(
    const float* __restrict__ resid, const float* __restrict__ text,
    const float* __restrict__ image, const float* __restrict__ ds,
    float* __restrict__ pred)
{
    __shared__ float red[8];
    const int b = blockIdx.x;
    const int t = threadIdx.x;
    const float d = ds[b];
    float v[3];
    float ss = 0.f;
    #pragma unroll
    for (int q = 0; q < 3; q++) {
        u64 off = (u64)b * FD + t + q * 256;
        float val = d * text[off] + (1.f - d) * image[off] + resid[off];
        v[q] = val;
        ss += val * val;
    }
    #pragma unroll
    for (int o = 16; o > 0; o >>= 1) ss += __shfl_xor_sync(0xffffffffu, ss, o);
    if ((t & 31) == 0) red[t >> 5] = ss;
    __syncthreads();
    if (t < 32) {
        float x = (t < 8) ? red[t] : 0.f;
        #pragma unroll
        for (int o = 4; o > 0; o >>= 1) x += __shfl_xor_sync(0xffffffffu, x, o);
        if (t == 0) red[0] = x;
    }
    __syncthreads();
    const float inv = 1.f / fmaxf(sqrtf(red[0]), 1e-12f);
    #pragma unroll
    for (int q = 0; q < 3; q++)
        pred[(u64)b * FD + t + q * 256] = v[q] * inv;
}

// ---------------------------------------------------------------------------
// out = normalize(in) row-wise (768 cols), one block per row
// ---------------------------------------------------------------------------
__global__ __launch_bounds__(256) void norm_kernel(const float* __restrict__ in,
                                                   float* __restrict__ outp)
{
    __shared__ float red[8];
    const int b = blockIdx.x;
    const int t = threadIdx.x;
    float v[3];
    float ss = 0.f;
    #pragma unroll
    for (int q = 0; q < 3; q++) {
        float val = in[(u64)b * FD + t + q * 256];
        v[q] = val;
        ss += val * val;
    }
    #pragma unroll
    for (int o = 16; o > 0; o >>= 1) ss += __shfl_xor_sync(0xffffffffu, ss, o);
    if ((t & 31) == 0) red[t >> 5] = ss;
    __syncthreads();
    if (t < 32) {
        float x = (t < 8) ? red[t] : 0.f;
        #pragma unroll
        for (int o = 4; o > 0; o >>= 1) x += __shfl_xor_sync(0xffffffffu, x, o);
        if (t == 0) red[0] = x;
    }
    __syncthreads();
    const float inv = 1.f / fmaxf(sqrtf(red[0]), 1e-12f);
    #pragma unroll
    for (int q = 0; q < 3; q++)
        outp[(u64)b * FD + t + q * 256] = v[q] * inv;
}

// ---------------------------------------------------------------------------
// Launch
// ---------------------------------------------------------------------------
extern "C" void kernel_launch(void* const* d_in, const int* in_sizes, int n_in,
                              void* d_out, int out_size)
{
    const float* image  = (const float*)d_in[0];
    const float* text   = (const float*)d_in[1];
    const float* target = (const float*)d_in[2];
    const float* Wt     = (const float*)d_in[3];
    const float* bt     = (const float*)d_in[4];
    const float* Wi     = (const float*)d_in[5];
    const float* bi     = (const float*)d_in[6];
    const float* dsW1   = (const float*)d_in[7];
    const float* dsb1   = (const float*)d_in[8];
    const float* dsW2   = (const float*)d_in[9];
    const float* dsb2   = (const float*)d_in[10];
    const float* expW   = (const float*)d_in[11];   // [E,H,2P] == [4096,1024]
    const float* expb   = (const float*)d_in[12];   // [E,H]    == [4096]
    const float* rtW1   = (const float*)d_in[13];
    const float* rtb1   = (const float*)d_in[14];
    const float* rtW2   = (const float*)d_in[15];
    const float* rtb2   = (const float*)d_in[16];
    const float* outW   = (const float*)d_in[17];
    const float* outb   = (const float*)d_in[18];
    const float* lscale = (const float*)d_in[19];
    float* out = (float*)d_out;

    float *comb, *rh, *eo, *fused, *dh, *resid, *pred, *tgt, *probs, *dsv;
    cudaGetSymbolAddress((void**)&comb,  g_comb);
    cudaGetSymbolAddress((void**)&rh,    g_rh);
    cudaGetSymbolAddress((void**)&eo,    g_eo);
    cudaGetSymbolAddress((void**)&fused, g_fused);
    cudaGetSymbolAddress((void**)&dh,    g_dh);
    cudaGetSymbolAddress((void**)&resid, g_resid);
    cudaGetSymbolAddress((void**)&pred,  g_pred);
    cudaGetSymbolAddress((void**)&tgt,   g_tgt);
    cudaGetSymbolAddress((void**)&probs, g_probs);
    cudaGetSymbolAddress((void**)&dsv,   g_ds);

    // 1) tp = gelu(text @ Wt^T + bt) -> comb[:, 0:512]
    sgemm_kernel<0><<<dim3(PD / BN, NB / BM), 256>>>(text, Wt, comb, FD, TWOP, 0, bt, nullptr);
    // 2) ip = gelu(image @ Wi^T + bi) -> comb[:, 512:1024]
    sgemm_kernel<0><<<dim3(PD / BN, NB / BM), 256>>>(image, Wi, comb, FD, TWOP, PD, bi, nullptr);
    // 3) router hidden = gelu(comb @ rt_W1^T + rt_b1)
    sgemm_kernel<0><<<dim3(RHD / BN, NB / BM), 256>>>(comb, rtW1, rh, TWOP, RHD, 0, rtb1, nullptr);
    // 4) router logits + softmax
    router_kernel<<<(NB * 32 + 255) / 256, 256>>>(rh, rtW2, rtb2, probs, out + PR_OFF);
    // 5) expert_out = gelu(comb @ exp_W_flat^T + exp_b_flat)   [B, 4096]
    sgemm_kernel<0><<<dim3((NE * HD) / BN, NB / BM), 256>>>(comb, expW, eo, TWOP, NE * HD, 0, expb, nullptr);
    // 6) fused hidden = probs-weighted mix
    expert_reduce_kernel<<<((u64)NB * HD + 255) / 256, 256>>>(eo, probs, fused);
    // 7) ds hidden = gelu(comb @ ds_W1^T + ds_b1)
    sgemm_kernel<0><<<dim3(HD / BN, NB / BM), 256>>>(comb, dsW1, dh, TWOP, HD, 0, dsb1, nullptr);
    // 8) ds = sigmoid(dh @ ds_W2^T + ds_b2)
    ds_kernel<<<(NB * 32 + 255) / 256, 256>>>(dh, dsW2, dsb2, dsv, out + DS_OFF);
    // 9) residual = fused @ out_W^T + out_b
    sgemm_kernel<1><<<dim3(FD / BN, NB / BM), 256>>>(fused, outW, resid, HD, FD, 0, outb, nullptr);
    // 10) pred = normalize(ds*text + (1-ds)*image + residual)
    fuse_norm_kernel<<<NB, 256>>>(resid, text, image, dsv, pred);
    // 11) tgt = normalize(target)
    norm_kernel<<<NT, 256>>>(target, tgt);
    // 12) logits = exp(logit_scale) * pred @ tgt^T  -> d_out[0 : B*T]
    sgemm_kernel<2><<<dim3(NT / BN, NB / BM), 256>>>(pred, tgt, out, FD, NT, 0, nullptr, lscale);
}

// round 13
// speedup vs baseline: 2.5381x; 2.5381x over previous
#include <cuda_runtime.h>
#include <cuda_bf16.h>
#include <stdint.h>
#include <math.h>

// ---------------------------------------------------------------------------
// Problem constants
// ---------------------------------------------------------------------------
#define NB   8192
#define NT   8192
#define FD   768
#define PD   512
#define HD   1024
#define NE   4
#define TWOP 1024
#define RHD  256

#define DS_OFF  (8192ull*8192ull)
#define PR_OFF  (8192ull*8192ull + 8192ull)

typedef unsigned long long u64;

// ---------------------------------------------------------------------------
// Scratch (device globals: allocation-free)
// ---------------------------------------------------------------------------
__device__ __nv_bfloat16 g_th [8192ull*768],  g_tl [8192ull*768];
__device__ __nv_bfloat16 g_ih [8192ull*768],  g_il [8192ull*768];
__device__ __nv_bfloat16 g_Wth[512*768],      g_Wtl[512*768];
__device__ __nv_bfloat16 g_Wih[512*768],      g_Wil[512*768];
__device__ __nv_bfloat16 g_rWh[256*1024],     g_rWl[256*1024];
__device__ __nv_bfloat16 g_eWh[4096ull*1024], g_eWl[4096ull*1024];
__device__ __nv_bfloat16 g_dWh[1024ull*1024], g_dWl[1024ull*1024];
__device__ __nv_bfloat16 g_oWh[768*1024],     g_oWl[768*1024];
__device__ __nv_bfloat16 g_cbh[8192ull*1024], g_cbl[8192ull*1024];
__device__ __nv_bfloat16 g_fuh[8192ull*1024], g_ful[8192ull*1024];
__device__ __nv_bfloat16 g_prh[8192ull*768],  g_prl[8192ull*768];
__device__ __nv_bfloat16 g_tgh[8192ull*768],  g_tgl[8192ull*768];
__device__ float g_rh   [8192ull*256];
__device__ float g_eo   [8192ull*4096];
__device__ float g_dh   [8192ull*1024];
__device__ float g_resid[8192ull*768];
__device__ float g_probs[8192ull*4];
__device__ float g_ds   [8192];

// ---------------------------------------------------------------------------
// Generic-ISA helpers (sm_80-level: ldmatrix / mma.sync / cp.async only)
// ---------------------------------------------------------------------------
__device__ __forceinline__ uint32_t smem_u32(const void* p) {
    uint32_t a;
    asm("{ .reg .u64 t; cvta.to.shared.u64 t, %1; cvt.u32.u64 %0, t; }"
        : "=r"(a) : "l"(p));
    return a;
}

__device__ __forceinline__ void ldsm4(uint32_t* r, uint32_t addr) {
    asm volatile("ldmatrix.sync.aligned.m8n8.x4.shared.b16 {%0,%1,%2,%3}, [%4];"
        : "=r"(r[0]), "=r"(r[1]), "=r"(r[2]), "=r"(r[3]) : "r"(addr));
}

__device__ __forceinline__ void mma16816(float* c, const uint32_t* a, const uint32_t* b) {
    asm volatile(
        "mma.sync.aligned.m16n8k16.row.col.f32.bf16.bf16.f32 "
        "{%0,%1,%2,%3},{%4,%5,%6,%7},{%8,%9},{%0,%1,%2,%3};"
        : "+f"(c[0]), "+f"(c[1]), "+f"(c[2]), "+f"(c[3])
        : "r"(a[0]), "r"(a[1]), "r"(a[2]), "r"(a[3]), "r"(b[0]), "r"(b[1]));
}

__device__ __forceinline__ void cp16(uint32_t saddr, const void* gptr) {
    asm volatile("cp.async.cg.shared.global [%0], [%1], 16;"
        :: "r"(saddr), "l"(gptr));
}
#define CP_COMMIT() asm volatile("cp.async.commit_group;")
#define CP_WAIT0()  asm volatile("cp.async.wait_group 0;")

__device__ __forceinline__ float gelu_exact(float x) {
    return 0.5f * x * (1.0f + erff(x * 0.70710678118654752440f));
}
__device__ __forceinline__ void split2(float x, __nv_bfloat16& h, __nv_bfloat16& l) {
    h = __float2bfloat16(x);
    l = __float2bfloat16(x - __bfloat162float(h));
}

// ---------------------------------------------------------------------------
// Split-bf16 HMMA GEMM: C[M,N] = epi( (Ah+Al)[M,K] @ (Bh+Bl)[N,K]^T )
//   via mma.sync m16n8k16 (hh + hl + lh products, fp32 accum).
// CTA 128x128, 8 warps (warp tile 64x32), BK=32, cp.async double buffer.
// Smem per buffer (32KB): Ah@0 Al@8K Bh@16K Bl@24K; row = 64B (32 bf16),
// 16B chunk swizzle: chunk' = chunk ^ ((row>>1)&3)  -> conflict-free ldmatrix.
// EPI: 0 = gelu(acc+bias[n]), 1 = acc+bias[n], 2 = exp(*scale_p)*acc
// OUT: 0 = fp32 C, 1 = split-bf16 (Ch, Cl)
// ---------------------------------------------------------------------------
#define GEMM_SMEM (65536 + 128)

template <int EPI, int OUT>
__global__ __launch_bounds__(256, 1) void gemm_mma(
    const __nv_bfloat16* __restrict__ Ah, const __nv_bfloat16* __restrict__ Al,
    const __nv_bfloat16* __restrict__ Bh, const __nv_bfloat16* __restrict__ Bl,
    float* __restrict__ C, __nv_bfloat16* __restrict__ Ch, __nv_bfloat16* __restrict__ Cl,
    int K, int ldc, int coloff,
    const float* __restrict__ bias, const float* __restrict__ scale_p)
{
    extern __shared__ char smraw[];
    const uint32_t sbase = (smem_u32(smraw) + 127u) & ~127u;

    const int tid  = threadIdx.x;
    const int wid  = tid >> 5;
    const int lane = tid & 31;
    const int wm   = wid >> 2;       // 0..1  (M)
    const int wn   = wid & 3;        // 0..3  (N)
    const int bm   = blockIdx.y * 128;
    const int bn   = blockIdx.x * 128;

    float acc[4][4][4];
    #pragma unroll
    for (int i = 0; i < 4; i++)
        #pragma unroll
        for (int j = 0; j < 4; j++)
            #pragma unroll
            for (int r = 0; r < 4; r++) acc[i][j][r] = 0.f;

    const __nv_bfloat16* src0 = Ah + (u64)bm * K;
    const __nv_bfloat16* src1 = Al + (u64)bm * K;
    const __nv_bfloat16* src2 = Bh + (u64)bn * K;
    const __nv_bfloat16* src3 = Bl + (u64)bn * K;

    // per-thread staging coords (2 chunks of 16B per tensor per k-chunk)
    const int q0row = tid >> 2,        q0c = tid & 3;
    const int q1row = (tid + 256) >> 2, q1c = tid & 3;  // +256 => +64 rows, same c
    const uint32_t sw0 = (uint32_t)(q0row * 64 + ((q0c ^ ((q0row >> 1) & 3)) << 4));
    const uint32_t sw1 = (uint32_t)(q1row * 64 + ((q1c ^ ((q1row >> 1) & 3)) << 4));

    // ldmatrix lane coords
    const int rA  = lane & 15;             // A rows 0..15 within atom
    const int cAx = (lane >> 4) & 1;       // A k-half select
    const int nB  = (lane & 7) | (((lane >> 4) & 1) << 3);
    const int cBx = (lane >> 3) & 1;

    const int nchunk = K >> 5;

#define LOAD_CHUNK(KB, BUFB) do {                                              \
        const int _kb = (KB); const uint32_t _bb = (BUFB);                     \
        cp16(_bb +     0 + sw0, src0 + (u64)q0row * K + _kb + q0c * 8);        \
        cp16(_bb +  8192 + sw0, src1 + (u64)q0row * K + _kb + q0c * 8);        \
        cp16(_bb + 16384 + sw0, src2 + (u64)q0row * K + _kb + q0c * 8);        \
        cp16(_bb + 24576 + sw0, src3 + (u64)q0row * K + _kb + q0c * 8);        \
        cp16(_bb +     0 + sw1, src0 + (u64)q1row * K + _kb + q1c * 8);        \
        cp16(_bb +  8192 + sw1, src1 + (u64)q1row * K + _kb + q1c * 8);        \
        cp16(_bb + 16384 + sw1, src2 + (u64)q1row * K + _kb + q1c * 8);        \
        cp16(_bb + 24576 + sw1, src3 + (u64)q1row * K + _kb + q1c * 8);        \
        CP_COMMIT();                                                           \
    } while (0)

    LOAD_CHUNK(0, sbase);

    for (int i = 0; i < nchunk; i++) {
        CP_WAIT0();
        __syncthreads();
        if (i + 1 < nchunk)
            LOAD_CHUNK((i + 1) << 5, sbase + (uint32_t)(((i + 1) & 1) * 32768));

        const uint32_t bufb = sbase + (uint32_t)((i & 1) * 32768);
        #pragma unroll
        for (int ks = 0; ks < 2; ks++) {
            uint32_t a[4][4], bh[4][2], t4[4];
            // Ah fragments (4 M-atoms)
            #pragma unroll
            for (int am = 0; am < 4; am++) {
                const int row = wm * 64 + am * 16 + rA;
                const int c   = ks * 2 + cAx;
                ldsm4(a[am], bufb + row * 64 + (uint32_t)((c ^ ((row >> 1) & 3)) << 4));
            }
            // Bh fragments (4 N-atoms via 2 x4 loads)
            #pragma unroll
            for (int np = 0; np < 2; np++) {
                const int row = wn * 32 + np * 16 + nB;
                const int c   = ks * 2 + cBx;
                ldsm4(t4, bufb + 16384 + row * 64 + (uint32_t)((c ^ ((row >> 1) & 3)) << 4));
                bh[np*2][0] = t4[0]; bh[np*2][1] = t4[1];
                bh[np*2+1][0] = t4[2]; bh[np*2+1][1] = t4[3];
            }
            // hh
            #pragma unroll
            for (int am = 0; am < 4; am++)
                #pragma unroll
                for (int an = 0; an < 4; an++)
                    mma16816(acc[am][an], a[am], bh[an]);
            // Bl fragments, then Ah x Bl
            uint32_t bl[4][2];
            #pragma unroll
            for (int np = 0; np < 2; np++) {
                const int row = wn * 32 + np * 16 + nB;
                const int c   = ks * 2 + cBx;
                ldsm4(t4, bufb + 24576 + row * 64 + (uint32_t)((c ^ ((row >> 1) & 3)) << 4));
                bl[np*2][0] = t4[0]; bl[np*2][1] = t4[1];
                bl[np*2+1][0] = t4[2]; bl[np*2+1][1] = t4[3];
            }
            #pragma unroll
            for (int am = 0; am < 4; am++)
                #pragma unroll
                for (int an = 0; an < 4; an++)
                    mma16816(acc[am][an], a[am], bl[an]);
            // Al fragments (overwrite a), then Al x Bh
            #pragma unroll
            for (int am = 0; am < 4; am++) {
                const int row = wm * 64 + am * 16 + rA;
                const int c   = ks * 2 + cAx;
                ldsm4(a[am], bufb + 8192 + row * 64 + (uint32_t)((c ^ ((row >> 1) & 3)) << 4));
            }
            #pragma unroll
            for (int am = 0; am < 4; am++)
                #pragma unroll
                for (int an = 0; an < 4; an++)
                    mma16816(acc[am][an], a[am], bh[an]);
        }
        __syncthreads();
    }
#undef LOAD_CHUNK

    // Epilogue: frag (g,tg): regs {c0,c1}=(g, tg*2..+1), {c2,c3}=(g+8, ...)
    float scale = 1.0f;
    if (EPI == 2) scale = expf(*scale_p);
    const int g  = lane >> 2;
    const int tg = lane & 3;
    #pragma unroll
    for (int am = 0; am < 4; am++) {
        const int row0 = bm + wm * 64 + am * 16 + g;
        #pragma unroll
        for (int an = 0; an < 4; an++) {
            const int coln = wn * 32 + an * 8 + tg * 2;      // local col (bias idx)
            float v[4];
            #pragma unroll
            for (int r = 0; r < 4; r++) {
                float x = acc[am][an][r];
                const int n = bn + coln + (r & 1);
                if (EPI == 0)      x = gelu_exact(x + __ldg(bias + n));
                else if (EPI == 1) x = x + __ldg(bias + n);
                else               x = x * scale;
                v[r] = x;
            }
            if (OUT == 0) {
                *(float2*)(C + (u64)row0 * ldc + coloff + bn + coln)       = make_float2(v[0], v[1]);
                *(float2*)(C + (u64)(row0 + 8) * ldc + coloff + bn + coln) = make_float2(v[2], v[3]);
            } else {
                __nv_bfloat16 h0,l0,h1,l1;
                split2(v[0], h0, l0); split2(v[1], h1, l1);
                __nv_bfloat162 H0; H0.x = h0; H0.y = h1;
                __nv_bfloat162 L0; L0.x = l0; L0.y = l1;
                *(__nv_bfloat162*)(Ch + (u64)row0 * ldc + coloff + bn + coln) = H0;
                *(__nv_bfloat162*)(Cl + (u64)row0 * ldc + coloff + bn + coln) = L0;
                split2(v[2], h0, l0); split2(v[3], h1, l1);
                H0.x = h0; H0.y = h1; L0.x = l0; L0.y = l1;
                *(__nv_bfloat162*)(Ch + (u64)(row0 + 8) * ldc + coloff + bn + coln) = H0;
                *(__nv_bfloat162*)(Cl + (u64)(row0 + 8) * ldc + coloff + bn + coln) = L0;
            }
        }
    }
}

// ---------------------------------------------------------------------------
// fp32 -> split bf16 (hi, lo), vectorized x4
// ---------------------------------------------------------------------------
__global__ void split_kernel(const float* __restrict__ in,
                             __nv_bfloat16* __restrict__ h,
                             __nv_bfloat16* __restrict__ l, int n4)
{
    int i = blockIdx.x * blockDim.x + threadIdx.x;
    if (i >= n4) return;
    float4 v = ((const float4*)in)[i];
    __nv_bfloat16 h0,l0,h1,l1,h2,l2,h3,l3;
    split2(v.x, h0, l0); split2(v.y, h1, l1);
    split2(v.z, h2, l2); split2(v.w, h3, l3);
    __nv_bfloat162 H0; H0.x = h0; H0.y = h1;
    __nv_bfloat162 H1; H1.x = h2; H1.y = h3;
    __nv_bfloat162 L0; L0.x = l0; L0.y = l1;
    __nv_bfloat162 L1; L1.x = l2; L1.y = l3;
    ((__nv_bfloat162*)h)[2*i]   = H0;
    ((__nv_bfloat162*)h)[2*i+1] = H1;
    ((__nv_bfloat162*)l)[2*i]   = L0;
    ((__nv_bfloat162*)l)[2*i+1] = L1;
}

// ---------------------------------------------------------------------------
// Router: logits = rh @ rt_W2^T + b2 ; softmax. One warp per row.
// ---------------------------------------------------------------------------
__global__ void router_kernel(const float* __restrict__ rh,
                              const float* __restrict__ W2,
                              const float* __restrict__ b2,
                              float* __restrict__ probs,
                              float* __restrict__ out_probs)
{
    int warp = (blockIdx.x * blockDim.x + threadIdx.x) >> 5;
    int lane = threadIdx.x & 31;
    if (warp >= NB) return;
    const float* r = rh + (u64)warp * RHD;
    float s0 = 0.f, s1 = 0.f, s2 = 0.f, s3 = 0.f;
    #pragma unroll
    for (int i = 0; i < RHD / 32; i++) {
        int c = lane + i * 32;
        float v = r[c];
        s0 += v * W2[c];
        s1 += v * W2[RHD + c];
        s2 += v * W2[2 * RHD + c];
        s3 += v * W2[3 * RHD + c];
    }
    #pragma unroll
    for (int o = 16; o > 0; o >>= 1) {
        s0 += __shfl_xor_sync(0xffffffffu, s0, o);
        s1 += __shfl_xor_sync(0xffffffffu, s1, o);
        s2 += __shfl_xor_sync(0xffffffffu, s2, o);
        s3 += __shfl_xor_sync(0xffffffffu, s3, o);
    }
    if (lane == 0) {
        float l0 = s0 + b2[0], l1 = s1 + b2[1], l2 = s2 + b2[2], l3 = s3 + b2[3];
        float m  = fmaxf(fmaxf(l0, l1), fmaxf(l2, l3));
        float e0 = expf(l0 - m), e1 = expf(l1 - m), e2 = expf(l2 - m), e3 = expf(l3 - m);
        float inv = 1.f / (e0 + e1 + e2 + e3);
        float4 p = make_float4(e0 * inv, e1 * inv, e2 * inv, e3 * inv);
        *(float4*)(probs + (u64)warp * 4) = p;
        *(float4*)(out_probs + (u64)warp * 4) = p;
    }
}

// ---------------------------------------------------------------------------
// ds = sigmoid(dh . W2 + b2). One warp per row.
// ---------------------------------------------------------------------------
__global__ void ds_kernel(const float* __restrict__ dh,
                          const float* __restrict__ W2,
                          const float* __restrict__ b2,
                          float* __restrict__ ds,
                          float* __restrict__ out_ds)
{
    int warp = (blockIdx.x * blockDim.x + threadIdx.x) >> 5;
    int lane = threadIdx.x & 31;
    if (warp >= NB) return;
    const float* r = dh + (u64)warp * HD;
    float s = 0.f;
    #pragma unroll
    for (int i = 0; i < HD / 32; i++) s += r[lane + i * 32] * W2[lane + i * 32];
    #pragma unroll
    for (int o = 16; o > 0; o >>= 1) s += __shfl_xor_sync(0xffffffffu, s, o);
    if (lane == 0) {
        float sg = 1.f / (1.f + expf(-(s + b2[0])));
        ds[warp] = sg;
        out_ds[warp] = sg;
    }
}

// ---------------------------------------------------------------------------
// fused[b,h] = sum_e probs[b,e]*eo[b,e*H+h] -> split bf16 out
// ---------------------------------------------------------------------------
__global__ void expert_reduce_kernel(const float* __restrict__ eo,
                                     const float* __restrict__ probs,
                                     __nv_bfloat16* __restrict__ fh,
                                     __nv_bfloat16* __restrict__ fl)
{
    u64 idx = (u64)blockIdx.x * blockDim.x + threadIdx.x;
    if (idx >= (u64)NB * HD) return;
    u64 b = idx >> 10;
    u64 h = idx & 1023u;
    const float* p = probs + b * 4;
    const float* e = eo + b * (u64)(NE * HD) + h;
    float v = p[0]*e[0] + p[1]*e[HD] + p[2]*e[2*HD] + p[3]*e[3*HD];
    __nv_bfloat16 hh, ll;
    split2(v, hh, ll);
    fh[idx] = hh; fl[idx] = ll;
}

// ---------------------------------------------------------------------------
// pred = normalize(ds*text + (1-ds)*image + resid) -> split bf16
// ---------------------------------------------------------------------------
__global__ __launch_bounds__(256) void fuse_norm_kernel(
    const float* __restrict__ resid, const float* __restrict__ text,
    const float* __restrict__ image, const float* __restrict__ ds,
    __nv_bfloat16* __restrict__ ph, __nv_bfloat16* __restrict__ pl)
{
    __shared__ float red[8];
    const int b = blockIdx.x;
    const int t = threadIdx.x;
    const float d = ds[b];
    float v[3];
    float ss = 0.f;
    #pragma unroll
    for (int q = 0; q < 3; q++) {
        u64 off = (u64)b * FD + t + q * 256;
        float val = d * text[off] + (1.f - d) * image[off] + resid[off];
        v[q] = val;
        ss += val * val;
    }
    #pragma unroll
    for (int o = 16; o > 0; o >>= 1) ss += __shfl_xor_sync(0xffffffffu, ss, o);
    if ((t & 31) == 0) red[t >> 5] = ss;
    __syncthreads();
    if (t < 32) {
        float x = (t < 8) ? red[t] : 0.f;
        #pragma unroll
        for (int o = 4; o > 0; o >>= 1) x += __shfl_xor_sync(0xffffffffu, x, o);
        if (t == 0) red[0] = x;
    }
    __syncthreads();
    const float inv = 1.f / fmaxf(sqrtf(red[0]), 1e-12f);
    #pragma unroll
    for (int q = 0; q < 3; q++) {
        __nv_bfloat16 hh, ll;
        split2(v[q] * inv, hh, ll);
        u64 off = (u64)b * FD + t + q * 256;
        ph[off] = hh; pl[off] = ll;
    }
}

// ---------------------------------------------------------------------------
// tgt = normalize(target) -> split bf16
// ---------------------------------------------------------------------------
__global__ __launch_bounds__(256) void norm_kernel(const float* __restrict__ in,
                                                   __nv_bfloat16* __restrict__ th,
                                                   __nv_bfloat16* __restrict__ tl)
{
    __shared__ float red[8];
    const int b = blockIdx.x;
    const int t = threadIdx.x;
    float v[3];
    float ss = 0.f;
    #pragma unroll
    for (int q = 0; q < 3; q++) {
        float val = in[(u64)b * FD + t + q * 256];
        v[q] = val;
        ss += val * val;
    }
    #pragma unroll
    for (int o = 16; o > 0; o >>= 1) ss += __shfl_xor_sync(0xffffffffu, ss, o);
    if ((t & 31) == 0) red[t >> 5] = ss;
    __syncthreads();
    if (t < 32) {
        float x = (t < 8) ? red[t] : 0.f;
        #pragma unroll
        for (int o = 4; o > 0; o >>= 1) x += __shfl_xor_sync(0xffffffffu, x, o);
        if (t == 0) red[0] = x;
    }
    __syncthreads();
    const float inv = 1.f / fmaxf(sqrtf(red[0]), 1e-12f);
    #pragma unroll
    for (int q = 0; q < 3; q++) {
        __nv_bfloat16 hh, ll;
        split2(v[q] * inv, hh, ll);
        u64 off = (u64)b * FD + t + q * 256;
        th[off] = hh; tl[off] = ll;
    }
}

// ---------------------------------------------------------------------------
// Launch
// ---------------------------------------------------------------------------
static inline void launch_split(const float* src, __nv_bfloat16* h,
                                __nv_bfloat16* l, u64 n) {
    int n4 = (int)(n >> 2);
    split_kernel<<<(n4 + 255) / 256, 256>>>(src, h, l, n4);
}

extern "C" void kernel_launch(void* const* d_in, const int* in_sizes, int n_in,
                              void* d_out, int out_size)
{
    const float* image  = (const float*)d_in[0];
    const float* text   = (const float*)d_in[1];
    const float* target = (const float*)d_in[2];
    const float* Wt     = (const float*)d_in[3];
    const float* bt     = (const float*)d_in[4];
    const float* Wi     = (const float*)d_in[5];
    const float* bi     = (const float*)d_in[6];
    const float* dsW1   = (const float*)d_in[7];
    const float* dsb1   = (const float*)d_in[8];
    const float* dsW2   = (const float*)d_in[9];
    const float* dsb2   = (const float*)d_in[10];
    const float* expW   = (const float*)d_in[11];
    const float* expb   = (const float*)d_in[12];
    const float* rtW1   = (const float*)d_in[13];
    const float* rtb1   = (const float*)d_in[14];
    const float* rtW2   = (const float*)d_in[15];
    const float* rtb2   = (const float*)d_in[16];
    const float* outW   = (const float*)d_in[17];
    const float* outb   = (const float*)d_in[18];
    const float* lscale = (const float*)d_in[19];
    float* out = (float*)d_out;

    __nv_bfloat16 *th,*tl,*ih,*il,*Wth,*Wtl,*Wih,*Wil,*rWh,*rWl,*eWh,*eWl;
    __nv_bfloat16 *dWh,*dWl,*oWh,*oWl,*cbh,*cbl,*fuh,*ful,*prh,*prl,*tgh,*tgl;
    float *rh,*eo,*dh,*resid,*probs,*dsv;
    cudaGetSymbolAddress((void**)&th,  g_th);  cudaGetSymbolAddress((void**)&tl,  g_tl);
    cudaGetSymbolAddress((void**)&ih,  g_ih);  cudaGetSymbolAddress((void**)&il,  g_il);
    cudaGetSymbolAddress((void**)&Wth, g_Wth); cudaGetSymbolAddress((void**)&Wtl, g_Wtl);
    cudaGetSymbolAddress((void**)&Wih, g_Wih); cudaGetSymbolAddress((void**)&Wil, g_Wil);
    cudaGetSymbolAddress((void**)&rWh, g_rWh); cudaGetSymbolAddress((void**)&rWl, g_rWl);
    cudaGetSymbolAddress((void**)&eWh, g_eWh); cudaGetSymbolAddress((void**)&eWl, g_eWl);
    cudaGetSymbolAddress((void**)&dWh, g_dWh); cudaGetSymbolAddress((void**)&dWl, g_dWl);
    cudaGetSymbolAddress((void**)&oWh, g_oWh); cudaGetSymbolAddress((void**)&oWl, g_oWl);
    cudaGetSymbolAddress((void**)&cbh, g_cbh); cudaGetSymbolAddress((void**)&cbl, g_cbl);
    cudaGetSymbolAddress((void**)&fuh, g_fuh); cudaGetSymbolAddress((void**)&ful, g_ful);
    cudaGetSymbolAddress((void**)&prh, g_prh); cudaGetSymbolAddress((void**)&prl, g_prl);
    cudaGetSymbolAddress((void**)&tgh, g_tgh); cudaGetSymbolAddress((void**)&tgl, g_tgl);
    cudaGetSymbolAddress((void**)&rh,    g_rh);
    cudaGetSymbolAddress((void**)&eo,    g_eo);
    cudaGetSymbolAddress((void**)&dh,    g_dh);
    cudaGetSymbolAddress((void**)&resid, g_resid);
    cudaGetSymbolAddress((void**)&probs, g_probs);
    cudaGetSymbolAddress((void**)&dsv,   g_ds);

    cudaFuncSetAttribute(gemm_mma<0,0>, cudaFuncAttributeMaxDynamicSharedMemorySize, GEMM_SMEM);
    cudaFuncSetAttribute(gemm_mma<0,1>, cudaFuncAttributeMaxDynamicSharedMemorySize, GEMM_SMEM);
    cudaFuncSetAttribute(gemm_mma<1,0>, cudaFuncAttributeMaxDynamicSharedMemorySize, GEMM_SMEM);
    cudaFuncSetAttribute(gemm_mma<2,0>, cudaFuncAttributeMaxDynamicSharedMemorySize, GEMM_SMEM);

    // ---- splits of inputs & weights ----
    launch_split(text,  th,  tl,  (u64)NB * FD);
    launch_split(image, ih,  il,  (u64)NB * FD);
    launch_split(Wt,    Wth, Wtl, (u64)PD * FD);
    launch_split(Wi,    Wih, Wil, (u64)PD * FD);
    launch_split(rtW1,  rWh, rWl, (u64)RHD * TWOP);
    launch_split(expW,  eWh, eWl, (u64)NE * HD * TWOP);
    launch_split(dsW1,  dWh, dWl, (u64)HD * TWOP);
    launch_split(outW,  oWh, oWl, (u64)FD * HD);

    // 1) tp = gelu(text @ Wt^T + bt) -> comb[:, 0:512] (split bf16)
    gemm_mma<0,1><<<dim3(PD/128, NB/128), 256, GEMM_SMEM>>>(
        th, tl, Wth, Wtl, nullptr, cbh, cbl, FD, TWOP, 0, bt, nullptr);
    // 2) ip = gelu(image @ Wi^T + bi) -> comb[:, 512:1024]
    gemm_mma<0,1><<<dim3(PD/128, NB/128), 256, GEMM_SMEM>>>(
        ih, il, Wih, Wil, nullptr, cbh, cbl, FD, TWOP, PD, bi, nullptr);
    // 3) router hidden = gelu(comb @ rt_W1^T + rt_b1)
    gemm_mma<0,0><<<dim3(RHD/128, NB/128), 256, GEMM_SMEM>>>(
        cbh, cbl, rWh, rWl, rh, nullptr, nullptr, TWOP, RHD, 0, rtb1, nullptr);
    // 4) router logits + softmax
    router_kernel<<<(NB * 32 + 255) / 256, 256>>>(rh, rtW2, rtb2, probs, out + PR_OFF);
    // 5) expert_out = gelu(comb @ exp_W^T + exp_b)  [B, 4096]
    gemm_mma<0,0><<<dim3((NE*HD)/128, NB/128), 256, GEMM_SMEM>>>(
        cbh, cbl, eWh, eWl, eo, nullptr, nullptr, TWOP, NE*HD, 0, expb, nullptr);
    // 6) fused hidden (split bf16 out)
    expert_reduce_kernel<<<((u64)NB * HD + 255) / 256, 256>>>(eo, probs, fuh, ful);
    // 7) ds hidden = gelu(comb @ ds_W1^T + ds_b1)
    gemm_mma<0,0><<<dim3(HD/128, NB/128), 256, GEMM_SMEM>>>(
        cbh, cbl, dWh, dWl, dh, nullptr, nullptr, TWOP, HD, 0, dsb1, nullptr);
    // 8) ds = sigmoid(dh @ ds_W2^T + ds_b2)
    ds_kernel<<<(NB * 32 + 255) / 256, 256>>>(dh, dsW2, dsb2, dsv, out + DS_OFF);
    // 9) residual = fused @ out_W^T + out_b
    gemm_mma<1,0><<<dim3(FD/128, NB/128), 256, GEMM_SMEM>>>(
        fuh, ful, oWh, oWl, resid, nullptr, nullptr, HD, FD, 0, outb, nullptr);
    // 10) pred = normalize(ds*text + (1-ds)*image + residual) (split bf16)
    fuse_norm_kernel<<<NB, 256>>>(resid, text, image, dsv, prh, prl);
    // 11) tgt = normalize(target) (split bf16)
    norm_kernel<<<NT, 256>>>(target, tgh, tgl);
    // 12) logits = exp(logit_scale) * pred @ tgt^T
    gemm_mma<2,0><<<dim3(NT/128, NB/128), 256, GEMM_SMEM>>>(
        prh, prl, tgh, tgl, out, nullptr, nullptr, FD, NT, 0, nullptr, lscale);
}

// round 14
// speedup vs baseline: 2.6453x; 1.0422x over previous
#include <cuda_runtime.h>
#include <cuda_bf16.h>
#include <stdint.h>
#include <math.h>

// ---------------------------------------------------------------------------
// Problem constants
// ---------------------------------------------------------------------------
#define NB   8192
#define NT   8192
#define FD   768
#define PD   512
#define HD   1024
#define NE   4
#define TWOP 1024
#define RHD  256

#define DS_OFF  (8192ull*8192ull)
#define PR_OFF  (8192ull*8192ull + 8192ull)

typedef unsigned long long u64;

// ---------------------------------------------------------------------------
// Scratch (device globals: allocation-free)
// ---------------------------------------------------------------------------
__device__ __nv_bfloat16 g_th [8192ull*768],  g_tl [8192ull*768];
__device__ __nv_bfloat16 g_ih [8192ull*768],  g_il [8192ull*768];
__device__ __nv_bfloat16 g_Wth[512*768],      g_Wtl[512*768];
__device__ __nv_bfloat16 g_Wih[512*768],      g_Wil[512*768];
__device__ __nv_bfloat16 g_rWh[256*1024],     g_rWl[256*1024];
__device__ __nv_bfloat16 g_eWh[4096ull*1024], g_eWl[4096ull*1024];
__device__ __nv_bfloat16 g_dWh[1024ull*1024], g_dWl[1024ull*1024];
__device__ __nv_bfloat16 g_oWh[768*1024],     g_oWl[768*1024];
__device__ __nv_bfloat16 g_cbh[8192ull*1024], g_cbl[8192ull*1024];
__device__ __nv_bfloat16 g_fuh[8192ull*1024], g_ful[8192ull*1024];
__device__ __nv_bfloat16 g_prh[8192ull*768],  g_prl[8192ull*768];
__device__ __nv_bfloat16 g_tgh[8192ull*768],  g_tgl[8192ull*768];
__device__ float g_rh   [8192ull*256];
__device__ float g_eo   [8192ull*4096];
__device__ float g_dh   [8192ull*1024];
__device__ float g_resid[8192ull*768];
__device__ float g_probs[8192ull*4];
__device__ float g_ds   [8192];

// ---------------------------------------------------------------------------
// Generic-ISA helpers (sm_80-level: ldmatrix / mma.sync / cp.async only)
// ---------------------------------------------------------------------------
__device__ __forceinline__ uint32_t smem_u32(const void* p) {
    uint32_t a;
    asm("{ .reg .u64 t; cvta.to.shared.u64 t, %1; cvt.u32.u64 %0, t; }"
        : "=r"(a) : "l"(p));
    return a;
}

__device__ __forceinline__ void ldsm4(uint32_t* r, uint32_t addr) {
    asm volatile("ldmatrix.sync.aligned.m8n8.x4.shared.b16 {%0,%1,%2,%3}, [%4];"
        : "=r"(r[0]), "=r"(r[1]), "=r"(r[2]), "=r"(r[3]) : "r"(addr));
}

__device__ __forceinline__ void mma16816(float* c, const uint32_t* a, const uint32_t* b) {
    asm volatile(
        "mma.sync.aligned.m16n8k16.row.col.f32.bf16.bf16.f32 "
        "{%0,%1,%2,%3},{%4,%5,%6,%7},{%8,%9},{%0,%1,%2,%3};"
        : "+f"(c[0]), "+f"(c[1]), "+f"(c[2]), "+f"(c[3])
        : "r"(a[0]), "r"(a[1]), "r"(a[2]), "r"(a[3]), "r"(b[0]), "r"(b[1]));
}

__device__ __forceinline__ void cp16(uint32_t saddr, const void* gptr) {
    asm volatile("cp.async.cg.shared.global [%0], [%1], 16;"
        :: "r"(saddr), "l"(gptr));
}
#define CP_COMMIT() asm volatile("cp.async.commit_group;")
#define CP_WAIT0()  asm volatile("cp.async.wait_group 0;")
#define CP_WAIT1()  asm volatile("cp.async.wait_group 1;")

__device__ __forceinline__ float gelu_exact(float x) {
    return 0.5f * x * (1.0f + erff(x * 0.70710678118654752440f));
}
__device__ __forceinline__ void split2(float x, __nv_bfloat16& h, __nv_bfloat16& l) {
    h = __float2bfloat16(x);
    l = __float2bfloat16(x - __bfloat162float(h));
}

// ---------------------------------------------------------------------------
// Split-bf16 HMMA GEMM: C[M,N] = epi( (Ah+Al)[M,K] @ (Bh+Bl)[N,K]^T )
//   via mma.sync m16n8k16 (hh + hl + lh products, fp32 accum).
// CTA 128x256, 8 warps (warp tile 64x64, grid 2x4), BK=32,
// cp.async 3-stage pipeline (wait_group 1 steady-state).
// Smem per buffer (48KB): Ah@0(8K) Al@8K Bh@16K(16K) Bl@32K(16K).
// Row = 64B (32 bf16), 16B-chunk swizzle: chunk' = chunk ^ ((row>>1)&3).
// EPI: 0 = gelu(acc+bias[n]), 1 = acc+bias[n], 2 = exp(*scale_p)*acc
// OUT: 0 = fp32 C, 1 = split-bf16 (Ch, Cl)
// ---------------------------------------------------------------------------
#define BUFSZ 49152
#define GEMM_SMEM (3 * BUFSZ + 128)

template <int EPI, int OUT>
__global__ __launch_bounds__(256, 1) void gemm_mma(
    const __nv_bfloat16* __restrict__ Ah, const __nv_bfloat16* __restrict__ Al,
    const __nv_bfloat16* __restrict__ Bh, const __nv_bfloat16* __restrict__ Bl,
    float* __restrict__ C, __nv_bfloat16* __restrict__ Ch, __nv_bfloat16* __restrict__ Cl,
    int K, int ldc, int coloff,
    const float* __restrict__ bias, const float* __restrict__ scale_p)
{
    extern __shared__ char smraw[];
    const uint32_t sbase = (smem_u32(smraw) + 127u) & ~127u;

    const int tid  = threadIdx.x;
    const int wid  = tid >> 5;
    const int lane = tid & 31;
    const int wm   = wid >> 2;       // 0..1  (M: 64 rows)
    const int wn   = wid & 3;        // 0..3  (N: 64 cols)
    const int bm   = blockIdx.y * 128;
    const int bn   = blockIdx.x * 256;

    float acc[4][8][4];
    #pragma unroll
    for (int i = 0; i < 4; i++)
        #pragma unroll
        for (int j = 0; j < 8; j++)
            #pragma unroll
            for (int r = 0; r < 4; r++) acc[i][j][r] = 0.f;

    const __nv_bfloat16* srcAh = Ah + (u64)bm * K;
    const __nv_bfloat16* srcAl = Al + (u64)bm * K;
    const __nv_bfloat16* srcBh = Bh + (u64)bn * K;
    const __nv_bfloat16* srcBl = Bl + (u64)bn * K;

    // staging: row0 = tid>>2 (0..63), c = tid&3; swizzle term constant mod 64 rows
    const int srow = tid >> 2;
    const int sc   = tid & 3;
    const uint32_t sw0 = (uint32_t)(srow * 64 + ((sc ^ ((srow >> 1) & 3)) << 4));
    const int gcol = sc * 8;   // bf16 col within 32-wide k-chunk

    // ldmatrix lane coords
    const int rA  = lane & 15;
    const int cAx = (lane >> 4) & 1;
    const int nB  = (lane & 7) | (((lane >> 4) & 1) << 3);
    const int cBx = (lane >> 3) & 1;

    const int nchunk = K >> 5;

#define LOAD_CHUNK(KB, BUFB) do {                                                   \
        const int _kb = (KB); const uint32_t _bb = (BUFB);                          \
        _Pragma("unroll")                                                           \
        for (int p = 0; p < 2; p++) {                                               \
            const u64 go = (u64)(srow + p * 64) * K + _kb + gcol;                   \
            cp16(_bb +        p * 4096 + sw0, srcAh + go);                          \
            cp16(_bb + 8192 + p * 4096 + sw0, srcAl + go);                          \
        }                                                                           \
        _Pragma("unroll")                                                           \
        for (int p = 0; p < 4; p++) {                                               \
            const u64 go = (u64)(srow + p * 64) * K + _kb + gcol;                   \
            cp16(_bb + 16384 + p * 4096 + sw0, srcBh + go);                         \
            cp16(_bb + 32768 + p * 4096 + sw0, srcBl + go);                         \
        }                                                                           \
        CP_COMMIT();                                                                \
    } while (0)

    LOAD_CHUNK(0, sbase);
    if (nchunk > 1) LOAD_CHUNK(32, sbase + BUFSZ);

    for (int i = 0; i < nchunk; i++) {
        if (i == nchunk - 1) { CP_WAIT0(); } else { CP_WAIT1(); }
        __syncthreads();
        if (i + 2 < nchunk)
            LOAD_CHUNK((i + 2) << 5, sbase + (uint32_t)(((i + 2) % 3) * BUFSZ));

        const uint32_t bufb = sbase + (uint32_t)((i % 3) * BUFSZ);
        #pragma unroll
        for (int ks = 0; ks < 2; ks++) {
            uint32_t a[4][4], bh[8][2], bl[8][2], t4[4];
            // Ah fragments (4 M-atoms of 16)
            #pragma unroll
            for (int am = 0; am < 4; am++) {
                const int row = wm * 64 + am * 16 + rA;
                const int c   = ks * 2 + cAx;
                ldsm4(a[am], bufb + row * 64 + (uint32_t)((c ^ ((row >> 1) & 3)) << 4));
            }
            // Bh fragments (8 N-atoms via 4 x4 loads)
            #pragma unroll
            for (int np = 0; np < 4; np++) {
                const int row = wn * 64 + np * 16 + nB;
                const int c   = ks * 2 + cBx;
                ldsm4(t4, bufb + 16384 + row * 64 + (uint32_t)((c ^ ((row >> 1) & 3)) << 4));
                bh[np*2][0] = t4[0]; bh[np*2][1] = t4[1];
                bh[np*2+1][0] = t4[2]; bh[np*2+1][1] = t4[3];
            }
            // Bl fragments
            #pragma unroll
            for (int np = 0; np < 4; np++) {
                const int row = wn * 64 + np * 16 + nB;
                const int c   = ks * 2 + cBx;
                ldsm4(t4, bufb + 32768 + row * 64 + (uint32_t)((c ^ ((row >> 1) & 3)) << 4));
                bl[np*2][0] = t4[0]; bl[np*2][1] = t4[1];
                bl[np*2+1][0] = t4[2]; bl[np*2+1][1] = t4[3];
            }
            // hh + hl
            #pragma unroll
            for (int am = 0; am < 4; am++)
                #pragma unroll
                for (int an = 0; an < 8; an++)
                    mma16816(acc[am][an], a[am], bh[an]);
            #pragma unroll
            for (int am = 0; am < 4; am++)
                #pragma unroll
                for (int an = 0; an < 8; an++)
                    mma16816(acc[am][an], a[am], bl[an]);
            // Al fragments (overwrite a), then lh
            #pragma unroll
            for (int am = 0; am < 4; am++) {
                const int row = wm * 64 + am * 16 + rA;
                const int c   = ks * 2 + cAx;
                ldsm4(a[am], bufb + 8192 + row * 64 + (uint32_t)((c ^ ((row >> 1) & 3)) << 4));
            }
            #pragma unroll
            for (int am = 0; am < 4; am++)
                #pragma unroll
                for (int an = 0; an < 8; an++)
                    mma16816(acc[am][an], a[am], bh[an]);
        }
        __syncthreads();
    }
#undef LOAD_CHUNK

    // Epilogue: frag (g,tg): regs {c0,c1}=(row g, cols tg*2..+1), {c2,c3}=(row g+8)
    float scale = 1.0f;
    if (EPI == 2) scale = expf(*scale_p);
    const int g  = lane >> 2;
    const int tg = lane & 3;
    #pragma unroll
    for (int am = 0; am < 4; am++) {
        const int row0 = bm + wm * 64 + am * 16 + g;
        #pragma unroll
        for (int an = 0; an < 8; an++) {
            const int coln = wn * 64 + an * 8 + tg * 2;
            float v[4];
            #pragma unroll
            for (int r = 0; r < 4; r++) {
                float x = acc[am][an][r];
                const int n = bn + coln + (r & 1);
                if (EPI == 0)      x = gelu_exact(x + __ldg(bias + n));
                else if (EPI == 1) x = x + __ldg(bias + n);
                else               x = x * scale;
                v[r] = x;
            }
            if (OUT == 0) {
                *(float2*)(C + (u64)row0 * ldc + coloff + bn + coln)       = make_float2(v[0], v[1]);
                *(float2*)(C + (u64)(row0 + 8) * ldc + coloff + bn + coln) = make_float2(v[2], v[3]);
            } else {
                __nv_bfloat16 h0,l0,h1,l1;
                split2(v[0], h0, l0); split2(v[1], h1, l1);
                __nv_bfloat162 H0; H0.x = h0; H0.y = h1;
                __nv_bfloat162 L0; L0.x = l0; L0.y = l1;
                *(__nv_bfloat162*)(Ch + (u64)row0 * ldc + coloff + bn + coln) = H0;
                *(__nv_bfloat162*)(Cl + (u64)row0 * ldc + coloff + bn + coln) = L0;
                split2(v[2], h0, l0); split2(v[3], h1, l1);
                H0.x = h0; H0.y = h1; L0.x = l0; L0.y = l1;
                *(__nv_bfloat162*)(Ch + (u64)(row0 + 8) * ldc + coloff + bn + coln) = H0;
                *(__nv_bfloat162*)(Cl + (u64)(row0 + 8) * ldc + coloff + bn + coln) = L0;
            }
        }
    }
}

// ---------------------------------------------------------------------------
// fp32 -> split bf16 (hi, lo), vectorized x4
// ---------------------------------------------------------------------------
__global__ void split_kernel(const float* __restrict__ in,
                             __nv_bfloat16* __restrict__ h,
                             __nv_bfloat16* __restrict__ l, int n4)
{
    int i = blockIdx.x * blockDim.x + threadIdx.x;
    if (i >= n4) return;
    float4 v = ((const float4*)in)[i];
    __nv_bfloat16 h0,l0,h1,l1,h2,l2,h3,l3;
    split2(v.x, h0, l0); split2(v.y, h1, l1);
    split2(v.z, h2, l2); split2(v.w, h3, l3);
    __nv_bfloat162 H0; H0.x = h0; H0.y = h1;
    __nv_bfloat162 H1; H1.x = h2; H1.y = h3;
    __nv_bfloat162 L0; L0.x = l0; L0.y = l1;
    __nv_bfloat162 L1; L1.x = l2; L1.y = l3;
    ((__nv_bfloat162*)h)[2*i]   = H0;
    ((__nv_bfloat162*)h)[2*i+1] = H1;
    ((__nv_bfloat162*)l)[2*i]   = L0;
    ((__nv_bfloat162*)l)[2*i+1] = L1;
}

// ---------------------------------------------------------------------------
// Router: logits = rh @ rt_W2^T + b2 ; softmax. One warp per row.
// ---------------------------------------------------------------------------
__global__ void router_kernel(const float* __restrict__ rh,
                              const float* __restrict__ W2,
                              const float* __restrict__ b2,
                              float* __restrict__ probs,
                              float* __restrict__ out_probs)
{
    int warp = (blockIdx.x * blockDim.x + threadIdx.x) >> 5;
    int lane = threadIdx.x & 31;
    if (warp >= NB) return;
    const float* r = rh + (u64)warp * RHD;
    float s0 = 0.f, s1 = 0.f, s2 = 0.f, s3 = 0.f;
    #pragma unroll
    for (int i = 0; i < RHD / 32; i++) {
        int c = lane + i * 32;
        float v = r[c];
        s0 += v * W2[c];
        s1 += v * W2[RHD + c];
        s2 += v * W2[2 * RHD + c];
        s3 += v * W2[3 * RHD + c];
    }
    #pragma unroll
    for (int o = 16; o > 0; o >>= 1) {
        s0 += __shfl_xor_sync(0xffffffffu, s0, o);
        s1 += __shfl_xor_sync(0xffffffffu, s1, o);
        s2 += __shfl_xor_sync(0xffffffffu, s2, o);
        s3 += __shfl_xor_sync(0xffffffffu, s3, o);
    }
    if (lane == 0) {
        float l0 = s0 + b2[0], l1 = s1 + b2[1], l2 = s2 + b2[2], l3 = s3 + b2[3];
        float m  = fmaxf(fmaxf(l0, l1), fmaxf(l2, l3));
        float e0 = expf(l0 - m), e1 = expf(l1 - m), e2 = expf(l2 - m), e3 = expf(l3 - m);
        float inv = 1.f / (e0 + e1 + e2 + e3);
        float4 p = make_float4(e0 * inv, e1 * inv, e2 * inv, e3 * inv);
        *(float4*)(probs + (u64)warp * 4) = p;
        *(float4*)(out_probs + (u64)warp * 4) = p;
    }
}

// ---------------------------------------------------------------------------
// ds = sigmoid(dh . W2 + b2). One warp per row.
// ---------------------------------------------------------------------------
__global__ void ds_kernel(const float* __restrict__ dh,
                          const float* __restrict__ W2,
                          const float* __restrict__ b2,
                          float* __restrict__ ds,
                          float* __restrict__ out_ds)
{
    int warp = (blockIdx.x * blockDim.x + threadIdx.x) >> 5;
    int lane = threadIdx.x & 31;
    if (warp >= NB) return;
    const float* r = dh + (u64)warp * HD;
    float s = 0.f;
    #pragma unroll
    for (int i = 0; i < HD / 32; i++) s += r[lane + i * 32] * W2[lane + i * 32];
    #pragma unroll
    for (int o = 16; o > 0; o >>= 1) s += __shfl_xor_sync(0xffffffffu, s, o);
    if (lane == 0) {
        float sg = 1.f / (1.f + expf(-(s + b2[0])));
        ds[warp] = sg;
        out_ds[warp] = sg;
    }
}

// ---------------------------------------------------------------------------
// fused[b,h] = sum_e probs[b,e]*eo[b,e*H+h] -> split bf16 out
// ---------------------------------------------------------------------------
__global__ void expert_reduce_kernel(const float* __restrict__ eo,
                                     const float* __restrict__ probs,
                                     __nv_bfloat16* __restrict__ fh,
                                     __nv_bfloat16* __restrict__ fl)
{
    u64 idx = (u64)blockIdx.x * blockDim.x + threadIdx.x;
    if (idx >= (u64)NB * HD) return;
    u64 b = idx >> 10;
    u64 h = idx & 1023u;
    const float* p = probs + b * 4;
    const float* e = eo + b * (u64)(NE * HD) + h;
    float v = p[0]*e[0] + p[1]*e[HD] + p[2]*e[2*HD] + p[3]*e[3*HD];
    __nv_bfloat16 hh, ll;
    split2(v, hh, ll);
    fh[idx] = hh; fl[idx] = ll;
}

// ---------------------------------------------------------------------------
// pred = normalize(ds*text + (1-ds)*image + resid) -> split bf16
// ---------------------------------------------------------------------------
__global__ __launch_bounds__(256) void fuse_norm_kernel(
    const float* __restrict__ resid, const float* __restrict__ text,
    const float* __restrict__ image, const float* __restrict__ ds,
    __nv_bfloat16* __restrict__ ph, __nv_bfloat16* __restrict__ pl)
{
    __shared__ float red[8];
    const int b = blockIdx.x;
    const int t = threadIdx.x;
    const float d = ds[b];
    float v[3];
    float ss = 0.f;
    #pragma unroll
    for (int q = 0; q < 3; q++) {
        u64 off = (u64)b * FD + t + q * 256;
        float val = d * text[off] + (1.f - d) * image[off] + resid[off];
        v[q] = val;
        ss += val * val;
    }
    #pragma unroll
    for (int o = 16; o > 0; o >>= 1) ss += __shfl_xor_sync(0xffffffffu, ss, o);
    if ((t & 31) == 0) red[t >> 5] = ss;
    __syncthreads();
    if (t < 32) {
        float x = (t < 8) ? red[t] : 0.f;
        #pragma unroll
        for (int o = 4; o > 0; o >>= 1) x += __shfl_xor_sync(0xffffffffu, x, o);
        if (t == 0) red[0] = x;
    }
    __syncthreads();
    const float inv = 1.f / fmaxf(sqrtf(red[0]), 1e-12f);
    #pragma unroll
    for (int q = 0; q < 3; q++) {
        __nv_bfloat16 hh, ll;
        split2(v[q] * inv, hh, ll);
        u64 off = (u64)b * FD + t + q * 256;
        ph[off] = hh; pl[off] = ll;
    }
}

// ---------------------------------------------------------------------------
// tgt = normalize(target) -> split bf16
// ---------------------------------------------------------------------------
__global__ __launch_bounds__(256) void norm_kernel(const float* __restrict__ in,
                                                   __nv_bfloat16* __restrict__ th,
                                                   __nv_bfloat16* __restrict__ tl)
{
    __shared__ float red[8];
    const int b = blockIdx.x;
    const int t = threadIdx.x;
    float v[3];
    float ss = 0.f;
    #pragma unroll
    for (int q = 0; q < 3; q++) {
        float val = in[(u64)b * FD + t + q * 256];
        v[q] = val;
        ss += val * val;
    }
    #pragma unroll
    for (int o = 16; o > 0; o >>= 1) ss += __shfl_xor_sync(0xffffffffu, ss, o);
    if ((t & 31) == 0) red[t >> 5] = ss;
    __syncthreads();
    if (t < 32) {
        float x = (t < 8) ? red[t] : 0.f;
        #pragma unroll
        for (int o = 4; o > 0; o >>= 1) x += __shfl_xor_sync(0xffffffffu, x, o);
        if (t == 0) red[0] = x;
    }
    __syncthreads();
    const float inv = 1.f / fmaxf(sqrtf(red[0]), 1e-12f);
    #pragma unroll
    for (int q = 0; q < 3; q++) {
        __nv_bfloat16 hh, ll;
        split2(v[q] * inv, hh, ll);
        u64 off = (u64)b * FD + t + q * 256;
        th[off] = hh; tl[off] = ll;
    }
}

// ---------------------------------------------------------------------------
// Launch
// ---------------------------------------------------------------------------
static inline void launch_split(const float* src, __nv_bfloat16* h,
                                __nv_bfloat16* l, u64 n) {
    int n4 = (int)(n >> 2);
    split_kernel<<<(n4 + 255) / 256, 256>>>(src, h, l, n4);
}

extern "C" void kernel_launch(void* const* d_in, const int* in_sizes, int n_in,
                              void* d_out, int out_size)
{
    const float* image  = (const float*)d_in[0];
    const float* text   = (const float*)d_in[1];
    const float* target = (const float*)d_in[2];
    const float* Wt     = (const float*)d_in[3];
    const float* bt     = (const float*)d_in[4];
    const float* Wi     = (const float*)d_in[5];
    const float* bi     = (const float*)d_in[6];
    const float* dsW1   = (const float*)d_in[7];
    const float* dsb1   = (const float*)d_in[8];
    const float* dsW2   = (const float*)d_in[9];
    const float* dsb2   = (const float*)d_in[10];
    const float* expW   = (const float*)d_in[11];
    const float* expb   = (const float*)d_in[12];
    const float* rtW1   = (const float*)d_in[13];
    const float* rtb1   = (const float*)d_in[14];
    const float* rtW2   = (const float*)d_in[15];
    const float* rtb2   = (const float*)d_in[16];
    const float* outW   = (const float*)d_in[17];
    const float* outb   = (const float*)d_in[18];
    const float* lscale = (const float*)d_in[19];
    float* out = (float*)d_out;

    __nv_bfloat16 *th,*tl,*ih,*il,*Wth,*Wtl,*Wih,*Wil,*rWh,*rWl,*eWh,*eWl;
    __nv_bfloat16 *dWh,*dWl,*oWh,*oWl,*cbh,*cbl,*fuh,*ful,*prh,*prl,*tgh,*tgl;
    float *rh,*eo,*dh,*resid,*probs,*dsv;
    cudaGetSymbolAddress((void**)&th,  g_th);  cudaGetSymbolAddress((void**)&tl,  g_tl);
    cudaGetSymbolAddress((void**)&ih,  g_ih);  cudaGetSymbolAddress((void**)&il,  g_il);
    cudaGetSymbolAddress((void**)&Wth, g_Wth); cudaGetSymbolAddress((void**)&Wtl, g_Wtl);
    cudaGetSymbolAddress((void**)&Wih, g_Wih); cudaGetSymbolAddress((void**)&Wil, g_Wil);
    cudaGetSymbolAddress((void**)&rWh, g_rWh); cudaGetSymbolAddress((void**)&rWl, g_rWl);
    cudaGetSymbolAddress((void**)&eWh, g_eWh); cudaGetSymbolAddress((void**)&eWl, g_eWl);
    cudaGetSymbolAddress((void**)&dWh, g_dWh); cudaGetSymbolAddress((void**)&dWl, g_dWl);
    cudaGetSymbolAddress((void**)&oWh, g_oWh); cudaGetSymbolAddress((void**)&oWl, g_oWl);
    cudaGetSymbolAddress((void**)&cbh, g_cbh); cudaGetSymbolAddress((void**)&cbl, g_cbl);
    cudaGetSymbolAddress((void**)&fuh, g_fuh); cudaGetSymbolAddress((void**)&ful, g_ful);
    cudaGetSymbolAddress((void**)&prh, g_prh); cudaGetSymbolAddress((void**)&prl, g_prl);
    cudaGetSymbolAddress((void**)&tgh, g_tgh); cudaGetSymbolAddress((void**)&tgl, g_tgl);
    cudaGetSymbolAddress((void**)&rh,    g_rh);
    cudaGetSymbolAddress((void**)&eo,    g_eo);
    cudaGetSymbolAddress((void**)&dh,    g_dh);
    cudaGetSymbolAddress((void**)&resid, g_resid);
    cudaGetSymbolAddress((void**)&probs, g_probs);
    cudaGetSymbolAddress((void**)&dsv,   g_ds);

    cudaFuncSetAttribute(gemm_mma<0,0>, cudaFuncAttributeMaxDynamicSharedMemorySize, GEMM_SMEM);
    cudaFuncSetAttribute(gemm_mma<0,1>, cudaFuncAttributeMaxDynamicSharedMemorySize, GEMM_SMEM);
    cudaFuncSetAttribute(gemm_mma<1,0>, cudaFuncAttributeMaxDynamicSharedMemorySize, GEMM_SMEM);
    cudaFuncSetAttribute(gemm_mma<2,0>, cudaFuncAttributeMaxDynamicSharedMemorySize, GEMM_SMEM);

    // ---- splits of inputs & weights ----
    launch_split(text,  th,  tl,  (u64)NB * FD);
    launch_split(image, ih,  il,  (u64)NB * FD);
    launch_split(Wt,    Wth, Wtl, (u64)PD * FD);
    launch_split(Wi,    Wih, Wil, (u64)PD * FD);
    launch_split(rtW1,  rWh, rWl, (u64)RHD * TWOP);
    launch_split(expW,  eWh, eWl, (u64)NE * HD * TWOP);
    launch_split(dsW1,  dWh, dWl, (u64)HD * TWOP);
    launch_split(outW,  oWh, oWl, (u64)FD * HD);

    // 1) tp = gelu(text @ Wt^T + bt) -> comb[:, 0:512] (split bf16)
    gemm_mma<0,1><<<dim3(PD/256, NB/128), 256, GEMM_SMEM>>>(
        th, tl, Wth, Wtl, nullptr, cbh, cbl, FD, TWOP, 0, bt, nullptr);
    // 2) ip = gelu(image @ Wi^T + bi) -> comb[:, 512:1024]
    gemm_mma<0,1><<<dim3(PD/256, NB/128), 256, GEMM_SMEM>>>(
        ih, il, Wih, Wil, nullptr, cbh, cbl, FD, TWOP, PD, bi, nullptr);
    // 3) router hidden = gelu(comb @ rt_W1^T + rt_b1)
    gemm_mma<0,0><<<dim3(RHD/256, NB/128), 256, GEMM_SMEM>>>(
        cbh, cbl, rWh, rWl, rh, nullptr, nullptr, TWOP, RHD, 0, rtb1, nullptr);
    // 4) router logits + softmax
    router_kernel<<<(NB * 32 + 255) / 256, 256>>>(rh, rtW2, rtb2, probs, out + PR_OFF);
    // 5) expert_out = gelu(comb @ exp_W^T + exp_b)  [B, 4096]
    gemm_mma<0,0><<<dim3((NE*HD)/256, NB/128), 256, GEMM_SMEM>>>(
        cbh, cbl, eWh, eWl, eo, nullptr, nullptr, TWOP, NE*HD, 0, expb, nullptr);
    // 6) fused hidden (split bf16 out)
    expert_reduce_kernel<<<((u64)NB * HD + 255) / 256, 256>>>(eo, probs, fuh, ful);
    // 7) ds hidden = gelu(comb @ ds_W1^T + ds_b1)
    gemm_mma<0,0><<<dim3(HD/256, NB/128), 256, GEMM_SMEM>>>(
        cbh, cbl, dWh, dWl, dh, nullptr, nullptr, TWOP, HD, 0, dsb1, nullptr);
    // 8) ds = sigmoid(dh @ ds_W2^T + ds_b2)
    ds_kernel<<<(NB * 32 + 255) / 256, 256>>>(dh, dsW2, dsb2, dsv, out + DS_OFF);
    // 9) residual = fused @ out_W^T + out_b
    gemm_mma<1,0><<<dim3(FD/256, NB/128), 256, GEMM_SMEM>>>(
        fuh, ful, oWh, oWl, resid, nullptr, nullptr, HD, FD, 0, outb, nullptr);
    // 10) pred = normalize(ds*text + (1-ds)*image + residual) (split bf16)
    fuse_norm_kernel<<<NB, 256>>>(resid, text, image, dsv, prh, prl);
    // 11) tgt = normalize(target) (split bf16)
    norm_kernel<<<NT, 256>>>(target, tgh, tgl);
    // 12) logits = exp(logit_scale) * pred @ tgt^T
    gemm_mma<2,0><<<dim3(NT/256, NB/128), 256, GEMM_SMEM>>>(
        prh, prl, tgh, tgl, out, nullptr, nullptr, FD, NT, 0, nullptr, lscale);
}